// round 16
// baseline (speedup 1.0000x reference)
#include <cuda_runtime.h>
#include <math.h>
#include <stdint.h>

// Problem constants
#define CB   4
#define CS   1024
#define CD   1024
#define CH   16
#define CHD  64
#define CL   6
#define COUT 512
#define CM   (CB*CS)
#define QKVS (3*CD)          // fused qkv row stride

// ---------------- scratch (device globals; no allocation allowed) ----------
__device__ float g_h  [CM*CD];
__device__ float g_hn [CM*CD];          // LN out, permuted-k (GEMM A operand)
__device__ float g_qkv[CM*QKVS];        // fused q|k|v, natural layout
__device__ float g_at [CM*CD];          // flash out, permuted-k (GEMM A operand)
__device__ float g_wc [5*CL*CD*CD + COUT*CD];   // tf32-rounded, permuted-k weights

// ---------------- helpers ----------------------------------------------------
__device__ __forceinline__ uint32_t f2tf(float f) {
    uint32_t u;
    asm("cvt.rna.tf32.f32 %0, %1;" : "=r"(u) : "f"(f));
    return u;
}
__device__ __forceinline__ float rnd(float f) { return __uint_as_float(f2tf(f)); }

__device__ __forceinline__ void mma_tf32(float* c, const uint32_t* a, const uint32_t* b) {
    asm volatile(
        "mma.sync.aligned.m16n8k8.row.col.f32.tf32.tf32.f32 "
        "{%0,%1,%2,%3}, {%4,%5,%6,%7}, {%8,%9}, {%0,%1,%2,%3};\n"
        : "+f"(c[0]), "+f"(c[1]), "+f"(c[2]), "+f"(c[3])
        : "r"(a[0]), "r"(a[1]), "r"(a[2]), "r"(a[3]),
          "r"(b[0]), "r"(b[1]));
}

__device__ __forceinline__ void cpasync16(uint32_t dst, const void* src) {
    asm volatile("cp.async.ca.shared.global [%0], [%1], 16;\n" :: "r"(dst), "l"(src));
}
__device__ __forceinline__ void cpasync16cg(uint32_t dst, const void* src) {
    asm volatile("cp.async.cg.shared.global [%0], [%1], 16;\n" :: "r"(dst), "l"(src));
}
#define CP_COMMIT() asm volatile("cp.async.commit_group;\n" ::: "memory")
#define CP_WAIT(n)  asm volatile("cp.async.wait_group %0;\n" :: "n"(n) : "memory")

// ---------------- weight pre-round + k-permute (fp32 -> tf32) ---------------
// Within each 32-wide k block, element k = 4q + r is stored at p = r*8 + q.
__global__ void __launch_bounds__(256) k_cvtw(const float* __restrict__ src,
                                              float* __restrict__ dst) {
    int i = blockIdx.x * 256 + threadIdx.x;          // float4 index
    float4 v = reinterpret_cast<const float4*>(src)[i];
    const size_t e0 = (size_t)i * 4;
    float* op = dst + (e0 & ~(size_t)31) + ((e0 >> 2) & 7);
    op[0]  = rnd(v.x);
    op[8]  = rnd(v.y);
    op[16] = rnd(v.z);
    op[24] = rnd(v.w);
}

// fused QKV weight convert: family f = blockIdx.y (0=q,1=k,2=v)
__global__ void __launch_bounds__(256) k_cvtw3(const float* __restrict__ wq,
                                               const float* __restrict__ wk,
                                               const float* __restrict__ wv,
                                               float* __restrict__ dst) {
    int i = blockIdx.x * 256 + threadIdx.x;          // float4 index over CL*CD*CD/4
    const float* src = blockIdx.y == 0 ? wq : (blockIdx.y == 1 ? wk : wv);
    float4 v = reinterpret_cast<const float4*>(src)[i];
    const size_t e0 = (size_t)i * 4;
    const size_t l  = e0 >> 20;
    const size_t w  = e0 & ((1u << 20) - 1);
    float* op = dst + l * (3u << 20) + ((size_t)blockIdx.y << 20)
                    + (w & ~(size_t)31) + ((w >> 2) & 7);
    op[0]  = rnd(v.x);
    op[8]  = rnd(v.y);
    op[16] = rnd(v.z);
    op[24] = rnd(v.w);
}

// ---------------- h = x + pe ------------------------------------------------
__global__ void __launch_bounds__(256) k_addpe(const float* __restrict__ x,
                                               const float* __restrict__ pe) {
    const int D4 = CD / 4;
    int i = blockIdx.x * 256 + threadIdx.x;
    float4 a = reinterpret_cast<const float4*>(x)[i];
    int row = i / D4;
    int pei = (row & (CS - 1)) * D4 + (i - row * D4);
    float4 p = reinterpret_cast<const float4*>(pe)[pei];
    a.x += p.x; a.y += p.y; a.z += p.z; a.w += p.w;
    reinterpret_cast<float4*>(g_h)[i] = a;
}

// ---------------- LayerNorm: warp-per-row, no block barriers ----------------
// 8 rows per 256-thread block; lane holds 8 float4 of its row; shfl reduce.
// Output tf32-rounded, permuted-k (same mapping as before).
__global__ void __launch_bounds__(256) k_ln(const float* __restrict__ in,
                                            float* __restrict__ out,
                                            const float* __restrict__ gw,
                                            const float* __restrict__ bw) {
    const int wid  = threadIdx.x >> 5;
    const int lane = threadIdx.x & 31;
    const int row  = blockIdx.x * 8 + wid;

    const float4* ip = reinterpret_cast<const float4*>(in + (size_t)row * CD);
    float4 v[8];
    float s = 0.f, q2 = 0.f;
#pragma unroll
    for (int i = 0; i < 8; i++) {
        v[i] = ip[i*32 + lane];
        s  += v[i].x + v[i].y + v[i].z + v[i].w;
        q2 += v[i].x*v[i].x + v[i].y*v[i].y + v[i].z*v[i].z + v[i].w*v[i].w;
    }
#pragma unroll
    for (int o = 16; o; o >>= 1) {
        s  += __shfl_xor_sync(0xffffffffu, s,  o);
        q2 += __shfl_xor_sync(0xffffffffu, q2, o);
    }
    const float mu  = s * (1.0f / CD);
    const float var = q2 * (1.0f / CD) - mu * mu;
    const float inv = rsqrtf(var + 1e-5f);

    const float4* gp = reinterpret_cast<const float4*>(gw);
    const float4* bp = reinterpret_cast<const float4*>(bw);
    float* orow = out + (size_t)row * CD;
#pragma unroll
    for (int i = 0; i < 8; i++) {
        const int idx = i*32 + lane;                 // float4 index in row
        float4 g4 = gp[idx];
        float4 b4 = bp[idx];
        float* op = orow + ((idx << 2) & ~31) + (idx & 7);
        op[0]  = rnd((v[i].x - mu) * inv * g4.x + b4.x);
        op[8]  = rnd((v[i].y - mu) * inv * g4.y + b4.y);
        op[16] = rnd((v[i].z - mu) * inv * g4.z + b4.z);
        op[24] = rnd((v[i].w - mu) * inv * g4.w + b4.w);
    }
}

// ---------------- Tensor-core GEMM: C[M,N] = A[M,K]*B[N,K]^T (+res,+round) --
// Permuted-k operands -> LDS.128 fragment loads. 128x128x32 tiles, 3-stage
// cp.async.cg pipeline (prefetch distance 2), one barrier per k-tile.
#define NSTR 36
#define NBUF (128*NSTR)
#define GSTAGES 3

__global__ void __launch_bounds__(256, 2) k_gemm_tc(const float* __restrict__ A,
                                                    const float* __restrict__ B,
                                                    const float* Res, float* C,
                                                    int N, int K, int addRes, int roundC) {
    extern __shared__ uint32_t sh[];
    const uint32_t shb = (uint32_t)__cvta_generic_to_shared(sh);

    const int tid  = threadIdx.x;
    const int lane = tid & 31;
    const int wid  = tid >> 5;
    const int g    = lane >> 2;
    const int tig  = lane & 3;
    const int m0   = (wid & 3) * 32;
    const int n0   = (wid >> 2) * 64;
    const int brow = blockIdx.y << 7;
    const int bcol = blockIdx.x << 7;

    const int rowb = tid >> 3;
    const int ch   = tid & 7;

    float acc[2][8][4] = {};
    const int nk = K >> 5;

    const float* Ag = A + (size_t)(brow + rowb) * K + ch*4;
    const float* Bg = B + (size_t)(bcol + rowb) * K + ch*4;

    auto stage = [&](int buf, int k0) {
        const uint32_t Ad = shb + (uint32_t)(buf * NBUF) * 4u;
        const uint32_t Bd = shb + (uint32_t)((GSTAGES + buf) * NBUF) * 4u;
#pragma unroll
        for (int i = 0; i < 4; i++) {
            const int r = rowb + i*32;
            cpasync16cg(Ad + (uint32_t)(r * NSTR + ch*4) * 4u, Ag + (size_t)(i*32) * K + k0);
            cpasync16cg(Bd + (uint32_t)(r * NSTR + ch*4) * 4u, Bg + (size_t)(i*32) * K + k0);
        }
    };

    stage(0, 0);
    CP_COMMIT();
    stage(1, 32);
    CP_COMMIT();

    int cur = 0;
    for (int kt = 0; kt < nk; kt++) {
        CP_WAIT(1);                         // tile kt resident (one group may fly)
        __syncthreads();
        // stage kt+2 into the buffer consumed at iter kt-1 (free post-sync)
        if (kt + 2 < nk) {
            int nb = cur + 2; if (nb >= GSTAGES) nb -= GSTAGES;
            stage(nb, (kt + 2) << 5);
            CP_COMMIT();
        }

        const uint32_t* Ac = sh + cur * NBUF;
        const uint32_t* Bc = sh + (GSTAGES + cur) * NBUF;
#pragma unroll
        for (int kh = 0; kh < 2; kh++) {
            uint4 aU[2][2];
#pragma unroll
            for (int mt = 0; mt < 2; mt++)
#pragma unroll
                for (int rr = 0; rr < 2; rr++) {
                    const int row = m0 + mt*16 + rr*8 + g;
                    aU[mt][rr] = *reinterpret_cast<const uint4*>(&Ac[row*NSTR + tig*8 + kh*4]);
                }
            uint4 bU[8];
#pragma unroll
            for (int nt = 0; nt < 8; nt++) {
                const int n = n0 + nt*8 + g;
                bU[nt] = *reinterpret_cast<const uint4*>(&Bc[n*NSTR + tig*8 + kh*4]);
            }
            uint32_t af0[2][4] = {{aU[0][0].x, aU[0][1].x, aU[0][0].y, aU[0][1].y},
                                  {aU[1][0].x, aU[1][1].x, aU[1][0].y, aU[1][1].y}};
            uint32_t af1[2][4] = {{aU[0][0].z, aU[0][1].z, aU[0][0].w, aU[0][1].w},
                                  {aU[1][0].z, aU[1][1].z, aU[1][0].w, aU[1][1].w}};
#pragma unroll
            for (int nt = 0; nt < 8; nt++) {
                uint32_t bf0[2] = {bU[nt].x, bU[nt].y};
                mma_tf32(acc[0][nt], af0[0], bf0);
                mma_tf32(acc[1][nt], af0[1], bf0);
                uint32_t bf1[2] = {bU[nt].z, bU[nt].w};
                mma_tf32(acc[0][nt], af1[0], bf1);
                mma_tf32(acc[1][nt], af1[1], bf1);
            }
        }
        if (++cur == GSTAGES) cur = 0;
    }

#pragma unroll
    for (int mt = 0; mt < 2; mt++) {
        const int row = brow + m0 + mt*16 + g;
#pragma unroll
        for (int nt = 0; nt < 8; nt++) {
            const int col = bcol + n0 + nt*8 + 2*tig;
            float2 v0 = make_float2(acc[mt][nt][0], acc[mt][nt][1]);
            float2 v1 = make_float2(acc[mt][nt][2], acc[mt][nt][3]);
            if (addRes) {
                float2 r0 = *reinterpret_cast<const float2*>(Res + (size_t)row * N + col);
                float2 r1 = *reinterpret_cast<const float2*>(Res + (size_t)(row+8) * N + col);
                v0.x += r0.x; v0.y += r0.y;
                v1.x += r1.x; v1.y += r1.y;
            }
            if (roundC) {
                v0.x = rnd(v0.x); v0.y = rnd(v0.y);
                v1.x = rnd(v1.x); v1.y = rnd(v1.y);
            }
            *reinterpret_cast<float2*>(C + (size_t)row * N + col)     = v0;
            *reinterpret_cast<float2*>(C + (size_t)(row+8) * N + col) = v1;
        }
    }
}

// ---------------- fused flash attention --------------------------------------
#define FSTR 72
#define FT   (64*FSTR)
__global__ void __launch_bounds__(128) k_flash() {
    extern __shared__ uint32_t fsh[];
    const uint32_t shb = (uint32_t)__cvta_generic_to_shared(fsh);
    uint32_t* Ps = fsh + 4*FT;

    const int qb = 15 - blockIdx.x;
    const int bh = blockIdx.y;
    const int b  = bh >> 4, h = bh & 15;

    const int tid  = threadIdx.x;
    const int lane = tid & 31;
    const int wid  = tid >> 5;
    const int g    = lane >> 2;
    const int tig  = lane & 3;

    const int r0 = tid >> 4;
    const int c4 = (tid & 15) << 2;

    const int rq  = wid*16 + g;
    const int swa = rq & 4;

    const float* Kg = g_qkv + ((size_t)(b*CS + r0)) * QKVS + CD   + h*64 + c4;
    const float* Vg = g_qkv + ((size_t)(b*CS + r0)) * QKVS + 2*CD + h*64 + c4;

    auto stageKV = [&](int buf, int kb) {
        const uint32_t Kd = shb + (uint32_t)(buf * FT) * 4u;
        const uint32_t Vd = shb + (uint32_t)((2 + buf) * FT) * 4u;
#pragma unroll
        for (int i = 0; i < 8; i++) {
            const int m = r0 + i*8;
            cpasync16(Kd + (uint32_t)(m*FSTR + (c4 ^ (m & 4))) * 4u,
                      Kg + (size_t)(kb*64 + i*8) * QKVS);
            cpasync16(Vd + (uint32_t)(m*FSTR + c4) * 4u,
                      Vg + (size_t)(kb*64 + i*8) * QKVS);
        }
    };

    stageKV(0, 0);
    CP_COMMIT();

    uint32_t qf[8][4];
    {
        const float* Qg = g_qkv + ((size_t)(b*CS + qb*64 + r0)) * QKVS + h*64 + c4;
#pragma unroll
        for (int i = 0; i < 8; i++) {
            const int m = r0 + i*8;
            *reinterpret_cast<float4*>(&Ps[m*FSTR + (c4 ^ (m & 4))]) =
                *reinterpret_cast<const float4*>(Qg + (size_t)(i*8) * QKVS);
        }
        __syncthreads();
#pragma unroll
        for (int k8 = 0; k8 < 8; k8++) {
            const int kk = k8*8;
            qf[k8][0] = Ps[rq*FSTR     + ((kk + tig)     ^ swa)];
            qf[k8][1] = Ps[(rq+8)*FSTR + ((kk + tig)     ^ swa)];
            qf[k8][2] = Ps[rq*FSTR     + ((kk + tig + 4) ^ swa)];
            qf[k8][3] = Ps[(rq+8)*FSTR + ((kk + tig + 4) ^ swa)];
        }
    }

    float accO[8][4] = {};
    float mrow[2] = {-1e30f, -1e30f};
    float lrow[2] = {0.f, 0.f};

    for (int kb = 0; kb <= qb; kb++) {
        const int cur = kb & 1;
        CP_WAIT(0);
        __syncthreads();
        if (kb < qb) {
            stageKV(1 - cur, kb + 1);
            CP_COMMIT();
        }

        const uint32_t* Ks = fsh + cur * FT;
        const uint32_t* Vs = fsh + (2 + cur) * FT;

        float accS[8][4] = {};
#pragma unroll
        for (int k8 = 0; k8 < 8; k8++) {
            const int kk = k8*8;
#pragma unroll
            for (int nt = 0; nt < 8; nt++) {
                const int n  = nt*8 + g;
                const int sw = n & 4;
                uint32_t bf[2];
                bf[0] = Ks[n*FSTR + ((kk + tig)     ^ sw)];
                bf[1] = Ks[n*FSTR + ((kk + tig + 4) ^ sw)];
                mma_tf32(accS[nt], qf[k8], bf);
            }
        }

        const float scale = 0.125f;
#pragma unroll
        for (int nt = 0; nt < 8; nt++) {
#pragma unroll
            for (int e = 0; e < 4; e++) accS[nt][e] *= scale;
            if (kb == qb) {
                const int col = nt*8 + 2*tig;
                if (col     > rq)   accS[nt][0] = -1e30f;
                if (col + 1 > rq)   accS[nt][1] = -1e30f;
                if (col     > rq+8) accS[nt][2] = -1e30f;
                if (col + 1 > rq+8) accS[nt][3] = -1e30f;
            }
        }

        float mn0 = mrow[0], mn1 = mrow[1];
#pragma unroll
        for (int nt = 0; nt < 8; nt++) {
            mn0 = fmaxf(mn0, fmaxf(accS[nt][0], accS[nt][1]));
            mn1 = fmaxf(mn1, fmaxf(accS[nt][2], accS[nt][3]));
        }
#pragma unroll
        for (int o = 1; o <= 2; o <<= 1) {
            mn0 = fmaxf(mn0, __shfl_xor_sync(0xffffffffu, mn0, o));
            mn1 = fmaxf(mn1, __shfl_xor_sync(0xffffffffu, mn1, o));
        }
        const float fac0 = __expf(mrow[0] - mn0);
        const float fac1 = __expf(mrow[1] - mn1);
        mrow[0] = mn0; mrow[1] = mn1;
        lrow[0] *= fac0; lrow[1] *= fac1;

        float ps0 = 0.f, ps1 = 0.f;
#pragma unroll
        for (int nt = 0; nt < 8; nt++) {
            uint32_t p0 = f2tf(__expf(accS[nt][0] - mn0));
            uint32_t p1 = f2tf(__expf(accS[nt][1] - mn0));
            uint32_t p2 = f2tf(__expf(accS[nt][2] - mn1));
            uint32_t p3 = f2tf(__expf(accS[nt][3] - mn1));
            ps0 += __uint_as_float(p0) + __uint_as_float(p1);
            ps1 += __uint_as_float(p2) + __uint_as_float(p3);
            const int col = (2*tig) ^ swa;
            *reinterpret_cast<uint2*>(&Ps[rq*FSTR     + nt*8 + col]) = make_uint2(p0, p1);
            *reinterpret_cast<uint2*>(&Ps[(rq+8)*FSTR + nt*8 + col]) = make_uint2(p2, p3);
            accO[nt][0] *= fac0; accO[nt][1] *= fac0;
            accO[nt][2] *= fac1; accO[nt][3] *= fac1;
        }
#pragma unroll
        for (int o = 1; o <= 2; o <<= 1) {
            ps0 += __shfl_xor_sync(0xffffffffu, ps0, o);
            ps1 += __shfl_xor_sync(0xffffffffu, ps1, o);
        }
        lrow[0] += ps0; lrow[1] += ps1;
        __syncwarp();

#pragma unroll
        for (int k8 = 0; k8 < 8; k8++) {
            const int kk = k8*8;
            uint32_t af[4];
            af[0] = Ps[rq*FSTR     + ((kk + tig)     ^ swa)];
            af[1] = Ps[(rq+8)*FSTR + ((kk + tig)     ^ swa)];
            af[2] = Ps[rq*FSTR     + ((kk + tig + 4) ^ swa)];
            af[3] = Ps[(rq+8)*FSTR + ((kk + tig + 4) ^ swa)];
#pragma unroll
            for (int nt = 0; nt < 8; nt++) {
                const int n = nt*8 + g;
                uint32_t bf[2];
                bf[0] = Vs[(kk + tig)     * FSTR + n];
                bf[1] = Vs[(kk + tig + 4) * FSTR + n];
                mma_tf32(accO[nt], af, bf);
            }
        }
    }

    // ---- normalize; store tf32-rounded, PERMUTED-K (feeds Wo GEMM as A) ----
    const float inv0 = 1.0f / lrow[0];
    const float inv1 = 1.0f / lrow[1];
    float* Og = g_at + ((size_t)(b*CS + qb*64 + rq)) * CD + h*64;
#pragma unroll
    for (int nt = 0; nt < 8; nt++) {
        const int c0 = nt*8 + 2*tig;
        const int c1 = c0 + 1;
        const int p0 = (c0 & ~31) | ((c0 & 3)*8 + ((c0 >> 2) & 7));
        const int p1 = (c1 & ~31) | ((c1 & 3)*8 + ((c1 >> 2) & 7));
        Og[p0] = rnd(accO[nt][0]*inv0);
        Og[p1] = rnd(accO[nt][1]*inv0);
        Og[(size_t)8*CD + p0] = rnd(accO[nt][2]*inv1);
        Og[(size_t)8*CD + p1] = rnd(accO[nt][3]*inv1);
    }
}

// ---------------- launch -----------------------------------------------------
extern "C" void kernel_launch(void* const* d_in, const int* in_sizes, int n_in,
                              void* d_out, int out_size) {
    const float* x    = (const float*)d_in[0];
    const float* pe   = (const float*)d_in[1];
    const float* ln1g = (const float*)d_in[3];
    const float* ln1b = (const float*)d_in[4];
    const float* wq   = (const float*)d_in[5];
    const float* wk   = (const float*)d_in[6];
    const float* wv   = (const float*)d_in[7];
    const float* wo   = (const float*)d_in[8];
    const float* ln2g = (const float*)d_in[9];
    const float* ln2b = (const float*)d_in[10];
    const float* wf   = (const float*)d_in[11];
    const float* lnfg = (const float*)d_in[12];
    const float* lnfb = (const float*)d_in[13];
    const float* wout = (const float*)d_in[14];

    float *ph, *phn, *pqkv, *pat, *pwc;
    cudaGetSymbolAddress((void**)&ph,   g_h);
    cudaGetSymbolAddress((void**)&phn,  g_hn);
    cudaGetSymbolAddress((void**)&pqkv, g_qkv);
    cudaGetSymbolAddress((void**)&pat,  g_at);
    cudaGetSymbolAddress((void**)&pwc,  g_wc);

    const size_t WSZ = (size_t)CL * CD * CD;
    float* cwqkv = pwc;
    float* cwo   = pwc + 3*WSZ;
    float* cwf   = pwc + 4*WSZ;
    float* cwout = pwc + 5*WSZ;

    const int gemmSmem  = 2 * GSTAGES * NBUF * (int)sizeof(uint32_t);  // 110592 B
    const int flashSmem = 5 * FT * (int)sizeof(uint32_t);              // 92160 B
    cudaFuncSetAttribute(k_gemm_tc, cudaFuncAttributeMaxDynamicSharedMemorySize, gemmSmem);
    cudaFuncSetAttribute(k_flash,   cudaFuncAttributeMaxDynamicSharedMemorySize, flashSmem);

    const int gW = (int)(WSZ / 4 / 256);
    k_cvtw3<<<dim3(gW, 3), 256>>>(wq, wk, wv, cwqkv);
    k_cvtw<<<gW, 256>>>(wo, cwo);
    k_cvtw<<<gW, 256>>>(wf, cwf);
    k_cvtw<<<(COUT*CD/4)/256, 256>>>(wout, cwout);

    k_addpe<<<(CM * CD / 4) / 256, 256>>>(x, pe);

    const dim3 gQKV(QKVS / 128, CM / 128);   // (24, 32)
    const dim3 gProj(CD / 128, CM / 128);    // (8, 32)
    const dim3 gOut (COUT / 128, CM / 128);  // (4, 32)
    const dim3 gFl  (CS / 64, CB * CH);
    const int  gLN  = CM / 8;                // 512 blocks, warp-per-row

    for (int l = 0; l < CL; l++) {
        const size_t od   = (size_t)l * CD;
        const size_t odd  = (size_t)l * CD * CD;
        const size_t odd3 = (size_t)l * 3 * CD * CD;
        k_ln<<<gLN, 256>>>(ph, phn, ln1g + od, ln1b + od);
        k_gemm_tc<<<gQKV, 256, gemmSmem>>>(phn, cwqkv + odd3, nullptr, pqkv, QKVS, CD, 0, 1);
        k_flash<<<gFl, 128, flashSmem>>>();
        k_gemm_tc<<<gProj, 256, gemmSmem>>>(pat, cwo + odd, ph, ph, CD, CD, 1, 0);
        k_ln<<<gLN, 256>>>(ph, phn, ln2g + od, ln2b + od);
        k_gemm_tc<<<gProj, 256, gemmSmem>>>(phn, cwf + odd, ph, ph, CD, CD, 1, 0);
    }
    k_ln<<<gLN, 256>>>(ph, phn, lnfg, lnfb);
    k_gemm_tc<<<gOut, 256, gemmSmem>>>(phn, cwout, nullptr, (float*)d_out, COUT, CD, 0, 0);
}